// round 1
// baseline (speedup 1.0000x reference)
#include <cuda_runtime.h>

#define D     128
#define NA    16384
#define NC    16384
#define NE    524288
#define TR    64      // edge/row tile per block
#define NT    256     // threads per block
#define KC    16      // k-chunk rows staged in smem
#define EPS   1e-5f

// Scratch (static device arrays; no allocation)
__device__ float g_qb[NA * D];    // relu(GN(agts@query_w)) @ ctx_w1[128:256]
__device__ float g_ctxc[NC * D];  // ctx @ ctx_w1[256:384]
__device__ float g_acc[NA * D];   // agts@agt_w, then scatter-accumulated

// ---------------------------------------------------------------------------
// acc[8][4] += in_s[64x128] @ W[128x128]   (W row-major, gmem)
// thread map: lane=c-group (4 consecutive cols), warp=8-row group
// ---------------------------------------------------------------------------
__device__ __forceinline__ void gemm_tile(const float* in_s,
                                          const float* __restrict__ W,
                                          float* wbuf, float acc[8][4],
                                          int e0, int c4, int tid)
{
    const float4* Wg = reinterpret_cast<const float4*>(W);
    float4* wb = reinterpret_cast<float4*>(wbuf);
    for (int kb = 0; kb < D; kb += KC) {
        __syncthreads();
        wb[tid]      = Wg[kb * (D / 4) + tid];
        wb[tid + NT] = Wg[kb * (D / 4) + tid + NT];
        __syncthreads();
#pragma unroll
        for (int kk = 0; kk < KC; kk++) {
            float4 w = wb[kk * (D / 4) + c4];
#pragma unroll
            for (int i = 0; i < 8; i++) {
                float h = in_s[(e0 + i) * D + kb + kk];   // warp-broadcast LDS
                acc[i][0] = fmaf(h, w.x, acc[i][0]);
                acc[i][1] = fmaf(h, w.y, acc[i][1]);
                acc[i][2] = fmaf(h, w.z, acc[i][2]);
                acc[i][3] = fmaf(h, w.w, acc[i][3]);
            }
        }
    }
}

__device__ __forceinline__ void zero_acc(float acc[8][4])
{
#pragma unroll
    for (int i = 0; i < 8; i++)
#pragma unroll
        for (int j = 0; j < 4; j++) acc[i][j] = 0.f;
}

__device__ __forceinline__ void store_acc(float* io, const float acc[8][4], int e0, int c4)
{
#pragma unroll
    for (int i = 0; i < 8; i++) {
        float4 v = make_float4(acc[i][0], acc[i][1], acc[i][2], acc[i][3]);
        *reinterpret_cast<float4*>(&io[(e0 + i) * D + c4 * 4]) = v;
    }
}

// rowwise GroupNorm(1,C) over 64 rows in smem, warp per row, optional relu
__device__ __forceinline__ void gn_rows(float* io,
                                        const float* __restrict__ g,
                                        const float* __restrict__ b,
                                        bool do_relu, int tid)
{
    int lane = tid & 31, w = tid >> 5;
    for (int r = w; r < TR; r += 8) {
        float v[4], s = 0.f, sq = 0.f;
#pragma unroll
        for (int j = 0; j < 4; j++) {
            v[j] = io[r * D + lane + 32 * j];
            s += v[j]; sq += v[j] * v[j];
        }
#pragma unroll
        for (int o = 16; o > 0; o >>= 1) {
            s  += __shfl_xor_sync(0xffffffffu, s, o);
            sq += __shfl_xor_sync(0xffffffffu, sq, o);
        }
        float mean = s * (1.f / D);
        float var  = sq * (1.f / D) - mean * mean;
        float rstd = rsqrtf(var + EPS);
#pragma unroll
        for (int j = 0; j < 4; j++) {
            int c = lane + 32 * j;
            float x = (v[j] - mean) * rstd * g[c] + b[c];
            io[r * D + c] = do_relu ? fmaxf(x, 0.f) : x;
        }
    }
}

// ---------------------------------------------------------------------------
// Node precompute: g_qb = relu(GN(agts @ query_w)) @ ctx_w1[128:256]
// ---------------------------------------------------------------------------
__global__ __launch_bounds__(NT) void k_qb(const float* __restrict__ agts,
                                           const float* __restrict__ query_w,
                                           const float* __restrict__ query_g,
                                           const float* __restrict__ query_b,
                                           const float* __restrict__ ctx_w1)
{
    __shared__ float io[TR * D];
    __shared__ float wbuf[KC * D];
    int tid = threadIdx.x;
    int r0 = blockIdx.x * TR;
    int lane = tid & 31, wid = tid >> 5;
    int c4 = lane, e0 = wid * 8;

    for (int idx = tid; idx < TR * D; idx += NT) io[idx] = agts[r0 * D + idx];

    float acc[8][4];
    zero_acc(acc);
    gemm_tile(io, query_w, wbuf, acc, e0, c4, tid);   // io fully read after loop
    __syncthreads();
    store_acc(io, acc, e0, c4);
    __syncthreads();
    gn_rows(io, query_g, query_b, true, tid);
    __syncthreads();

    zero_acc(acc);
    gemm_tile(io, ctx_w1 + D * D, wbuf, acc, e0, c4, tid);
#pragma unroll
    for (int i = 0; i < 8; i++) {
        float4 v = make_float4(acc[i][0], acc[i][1], acc[i][2], acc[i][3]);
        *reinterpret_cast<float4*>(&g_qb[(r0 + e0 + i) * D + c4 * 4]) = v;
    }
}

// g_acc = agts @ agt_w
__global__ __launch_bounds__(NT) void k_accinit(const float* __restrict__ agts,
                                                const float* __restrict__ agt_w)
{
    __shared__ float io[TR * D];
    __shared__ float wbuf[KC * D];
    int tid = threadIdx.x;
    int r0 = blockIdx.x * TR;
    int lane = tid & 31, wid = tid >> 5;
    int c4 = lane, e0 = wid * 8;

    for (int idx = tid; idx < TR * D; idx += NT) io[idx] = agts[r0 * D + idx];

    float acc[8][4];
    zero_acc(acc);
    gemm_tile(io, agt_w, wbuf, acc, e0, c4, tid);
#pragma unroll
    for (int i = 0; i < 8; i++) {
        float4 v = make_float4(acc[i][0], acc[i][1], acc[i][2], acc[i][3]);
        *reinterpret_cast<float4*>(&g_acc[(r0 + e0 + i) * D + c4 * 4]) = v;
    }
}

// g_ctxc = ctx @ ctx_w1[256:384]
__global__ __launch_bounds__(NT) void k_ctxc(const float* __restrict__ ctx,
                                             const float* __restrict__ ctx_w1)
{
    __shared__ float io[TR * D];
    __shared__ float wbuf[KC * D];
    int tid = threadIdx.x;
    int r0 = blockIdx.x * TR;
    int lane = tid & 31, wid = tid >> 5;
    int c4 = lane, e0 = wid * 8;

    for (int idx = tid; idx < TR * D; idx += NT) io[idx] = ctx[r0 * D + idx];

    float acc[8][4];
    zero_acc(acc);
    gemm_tile(io, ctx_w1 + 2 * D * D, wbuf, acc, e0, c4, tid);
#pragma unroll
    for (int i = 0; i < 8; i++) {
        float4 v = make_float4(acc[i][0], acc[i][1], acc[i][2], acc[i][3]);
        *reinterpret_cast<float4*>(&g_ctxc[(r0 + e0 + i) * D + c4 * 4]) = v;
    }
}

// ---------------------------------------------------------------------------
// Fused per-edge pipeline: dist MLP -> concat GEMM -> ctx_w2 -> scatter-add
// ---------------------------------------------------------------------------
__global__ __launch_bounds__(NT) void k_edge(const float* __restrict__ agt_ctrs,
                                             const float* __restrict__ ctx_ctrs,
                                             const int* __restrict__ hi,
                                             const int* __restrict__ wi,
                                             const float* __restrict__ dist_w1,
                                             const float* __restrict__ dist_b1,
                                             const float* __restrict__ dist_w2,
                                             const float* __restrict__ dist_g2,
                                             const float* __restrict__ dist_b2,
                                             const float* __restrict__ ctx_w1,
                                             const float* __restrict__ ctx_g1,
                                             const float* __restrict__ ctx_b1,
                                             const float* __restrict__ ctx_w2)
{
    __shared__ float io[TR * D];
    __shared__ float wbuf[KC * D];
    __shared__ int hi_s[TR], wi_s[TR];
    __shared__ float d2s[TR * 2];

    int tid = threadIdx.x;
    int ebase = blockIdx.x * TR;
    int lane = tid & 31, wid = tid >> 5;
    int c4 = lane, e0 = wid * 8;

    if (tid < TR) {
        int h = hi[ebase + tid], w = wi[ebase + tid];
        hi_s[tid] = h; wi_s[tid] = w;
        d2s[tid * 2 + 0] = agt_ctrs[h * 2 + 0] - ctx_ctrs[w * 2 + 0];
        d2s[tid * 2 + 1] = agt_ctrs[h * 2 + 1] - ctx_ctrs[w * 2 + 1];
    }
    __syncthreads();

    // dist layer 1: relu(d2 @ dist_w1 + b1)
    for (int idx = tid; idx < TR * D; idx += NT) {
        int e = idx >> 7, c = idx & 127;
        float v = d2s[e * 2] * dist_w1[c] + d2s[e * 2 + 1] * dist_w1[D + c] + dist_b1[c];
        io[idx] = fmaxf(v, 0.f);
    }
    // (first __syncthreads inside gemm_tile covers the writes above)

    float acc[8][4];

    // dist layer 2 + GN + relu
    zero_acc(acc);
    gemm_tile(io, dist_w2, wbuf, acc, e0, c4, tid);
    __syncthreads();
    store_acc(io, acc, e0, c4);
    __syncthreads();
    gn_rows(io, dist_g2, dist_b2, true, tid);
    __syncthreads();

    // concat GEMM: d @ W_A + qb[hi] + ctxc[wi], then GN + relu
    zero_acc(acc);
    gemm_tile(io, ctx_w1, wbuf, acc, e0, c4, tid);
#pragma unroll
    for (int i = 0; i < 8; i++) {
        const float4 qv = *reinterpret_cast<const float4*>(&g_qb[hi_s[e0 + i] * D + c4 * 4]);
        const float4 cv = *reinterpret_cast<const float4*>(&g_ctxc[wi_s[e0 + i] * D + c4 * 4]);
        acc[i][0] += qv.x + cv.x;
        acc[i][1] += qv.y + cv.y;
        acc[i][2] += qv.z + cv.z;
        acc[i][3] += qv.w + cv.w;
    }
    __syncthreads();
    store_acc(io, acc, e0, c4);
    __syncthreads();
    gn_rows(io, ctx_g1, ctx_b1, true, tid);
    __syncthreads();

    // ctx_w2 GEMM + scatter-add
    zero_acc(acc);
    gemm_tile(io, ctx_w2, wbuf, acc, e0, c4, tid);
#pragma unroll
    for (int i = 0; i < 8; i++) {
        int row = hi_s[e0 + i];
#pragma unroll
        for (int j = 0; j < 4; j++)
            atomicAdd(&g_acc[row * D + c4 * 4 + j], acc[i][j]);
    }
}

// ---------------------------------------------------------------------------
// Final: a = relu(GN(acc)); out = relu(GN(a @ lin_w) + agts)
// ---------------------------------------------------------------------------
__global__ __launch_bounds__(NT) void k_final(const float* __restrict__ agts,
                                              const float* __restrict__ norm_g,
                                              const float* __restrict__ norm_b,
                                              const float* __restrict__ lin_w,
                                              const float* __restrict__ lin_g,
                                              const float* __restrict__ lin_b,
                                              float* __restrict__ out)
{
    __shared__ float io[TR * D];
    __shared__ float wbuf[KC * D];
    int tid = threadIdx.x;
    int r0 = blockIdx.x * TR;
    int lane = tid & 31, wid = tid >> 5;
    int c4 = lane, e0 = wid * 8;

    for (int idx = tid; idx < TR * D; idx += NT) io[idx] = g_acc[r0 * D + idx];
    __syncthreads();
    gn_rows(io, norm_g, norm_b, true, tid);
    __syncthreads();

    float acc[8][4];
    zero_acc(acc);
    gemm_tile(io, lin_w, wbuf, acc, e0, c4, tid);
    __syncthreads();
    store_acc(io, acc, e0, c4);
    __syncthreads();

    // final GN (no act) + residual + relu, fused
    for (int r = wid; r < TR; r += 8) {
        float v[4], s = 0.f, sq = 0.f;
#pragma unroll
        for (int j = 0; j < 4; j++) {
            v[j] = io[r * D + lane + 32 * j];
            s += v[j]; sq += v[j] * v[j];
        }
#pragma unroll
        for (int o = 16; o > 0; o >>= 1) {
            s  += __shfl_xor_sync(0xffffffffu, s, o);
            sq += __shfl_xor_sync(0xffffffffu, sq, o);
        }
        float mean = s * (1.f / D);
        float var  = sq * (1.f / D) - mean * mean;
        float rstd = rsqrtf(var + EPS);
#pragma unroll
        for (int j = 0; j < 4; j++) {
            int c = lane + 32 * j;
            float x = (v[j] - mean) * rstd * lin_g[c] + lin_b[c];
            float res = agts[(r0 + r) * D + c];
            out[(r0 + r) * D + c] = fmaxf(x + res, 0.f);
        }
    }
}

// ---------------------------------------------------------------------------
extern "C" void kernel_launch(void* const* d_in, const int* in_sizes, int n_in,
                              void* d_out, int out_size)
{
    const float* agts     = (const float*)d_in[0];
    const float* ctx      = (const float*)d_in[1];
    const float* agt_ctrs = (const float*)d_in[2];
    const float* ctx_ctrs = (const float*)d_in[3];
    const int*   hi       = (const int*)d_in[4];
    const int*   wi       = (const int*)d_in[5];
    const float* dist_w1  = (const float*)d_in[6];
    const float* dist_b1  = (const float*)d_in[7];
    const float* dist_w2  = (const float*)d_in[8];
    const float* dist_g2  = (const float*)d_in[9];
    const float* dist_b2  = (const float*)d_in[10];
    const float* query_w  = (const float*)d_in[11];
    const float* query_g  = (const float*)d_in[12];
    const float* query_b  = (const float*)d_in[13];
    const float* ctx_w1   = (const float*)d_in[14];
    const float* ctx_g1   = (const float*)d_in[15];
    const float* ctx_b1   = (const float*)d_in[16];
    const float* ctx_w2   = (const float*)d_in[17];
    const float* agt_w    = (const float*)d_in[18];
    const float* norm_g   = (const float*)d_in[19];
    const float* norm_b   = (const float*)d_in[20];
    const float* lin_w    = (const float*)d_in[21];
    const float* lin_g    = (const float*)d_in[22];
    const float* lin_b    = (const float*)d_in[23];
    float* out = (float*)d_out;

    k_qb<<<NA / TR, NT>>>(agts, query_w, query_g, query_b, ctx_w1);
    k_accinit<<<NA / TR, NT>>>(agts, agt_w);
    k_ctxc<<<NC / TR, NT>>>(ctx, ctx_w1);
    k_edge<<<NE / TR, NT>>>(agt_ctrs, ctx_ctrs, hi, wi,
                            dist_w1, dist_b1, dist_w2, dist_g2, dist_b2,
                            ctx_w1, ctx_g1, ctx_b1, ctx_w2);
    k_final<<<NA / TR, NT>>>(agts, norm_g, norm_b, lin_w, lin_g, lin_b, out);
}

// round 4
// speedup vs baseline: 2.0839x; 2.0839x over previous
#include <cuda_runtime.h>
#include <cuda_bf16.h>
#include <cstdint>

#define D     128
#define NA    16384
#define NC    16384
#define NE    524288
#define TR    64
#define NT    256
#define KC    16
#define TRE   128
#define EPS   1e-5f

// ---------------------------------------------------------------------------
// device scratch (no allocation)
// ---------------------------------------------------------------------------
__device__ __align__(16) float g_qb[NA * D];    // relu(GN(agts@query_w)) @ ctx_w1[128:256]
__device__ __align__(16) float g_ctxc[NC * D];  // ctx @ ctx_w1[256:384]
__device__ __align__(16) float g_acc[NA * D];   // agts@agt_w + scattered edge output

// ---------------------------------------------------------------------------
// helpers
// ---------------------------------------------------------------------------
__device__ __forceinline__ uint32_t smem_u32(const void* p) {
    uint32_t a;
    asm("{ .reg .u64 t; cvta.to.shared.u64 t, %1; cvt.u32.u64 %0, t; }" : "=r"(a) : "l"(p));
    return a;
}

__device__ __forceinline__ void mma16816(float c[4], const uint32_t a[4], const uint32_t b[2]) {
    asm volatile(
        "mma.sync.aligned.m16n8k16.row.col.f32.bf16.bf16.f32 "
        "{%0,%1,%2,%3}, {%4,%5,%6,%7}, {%8,%9}, {%0,%1,%2,%3};"
        : "+f"(c[0]), "+f"(c[1]), "+f"(c[2]), "+f"(c[3])
        : "r"(a[0]), "r"(a[1]), "r"(a[2]), "r"(a[3]), "r"(b[0]), "r"(b[1]));
}

__device__ __forceinline__ void ldsm_x4_t(uint32_t r[4], uint32_t addr) {
    asm volatile("ldmatrix.sync.aligned.m8n8.x4.trans.shared.b16 {%0,%1,%2,%3}, [%4];"
                 : "=r"(r[0]), "=r"(r[1]), "=r"(r[2]), "=r"(r[3]) : "r"(addr));
}

__device__ __forceinline__ void red4(float* p, float a, float b, float c, float d) {
    asm volatile("red.global.add.v4.f32 [%0], {%1,%2,%3,%4};"
                 :: "l"(p), "f"(a), "f"(b), "f"(c), "f"(d) : "memory");
}

__device__ __forceinline__ void split_pack(float x0, float x1, uint32_t& hp, uint32_t& lp) {
    __nv_bfloat16 h0 = __float2bfloat16(x0);
    __nv_bfloat16 h1 = __float2bfloat16(x1);
    float r0 = x0 - __bfloat162float(h0);
    float r1 = x1 - __bfloat162float(h1);
    __nv_bfloat16 l0 = __float2bfloat16(r0);
    __nv_bfloat16 l1 = __float2bfloat16(r1);
    hp = (uint32_t)__bfloat16_as_ushort(h0) | ((uint32_t)__bfloat16_as_ushort(h1) << 16);
    lp = (uint32_t)__bfloat16_as_ushort(l0) | ((uint32_t)__bfloat16_as_ushort(l1) << 16);
}

// ---------------------------------------------------------------------------
// k_edge_mma smem layout (bytes): wbuf_hi 32KB | wbuf_lo 32KB | ids | d2
// W stored as bf16 [k][n] with 16B-group XOR swizzle: group (k, nt) at
// k*256 + ((nt ^ (k&7))<<4)  -> ldmatrix row addresses hit distinct banks.
// ---------------------------------------------------------------------------
#define SW_LO    32768
#define SM_HIS   65536
#define SM_WIS   66048
#define SM_D2    66560
#define SMEM_EDGE 67840

__device__ __forceinline__ void copy_w_split(const float* __restrict__ Wsrc, char* smem, int tid) {
    const float4* Wg = (const float4*)Wsrc;
#pragma unroll
    for (int it = 0; it < 16; it++) {
        int idx = it * 256 + tid;
        int k = idx >> 5, nq = idx & 31;
        float4 v = Wg[idx];
        uint32_t h01, l01, h23, l23;
        split_pack(v.x, v.y, h01, l01);
        split_pack(v.z, v.w, h23, l23);
        uint32_t off = (uint32_t)(k * 256 + (((nq >> 1) ^ (k & 7)) << 4) + (nq & 1) * 8);
        *(uint2*)(smem + off)         = make_uint2(h01, h23);
        *(uint2*)(smem + SW_LO + off) = make_uint2(l01, l23);
    }
}

// C[16 tiles][4] += A(hi/lo) @ B(hi/lo), 3-product split
__device__ __forceinline__ void mma_stage(float c[16][4],
                                          const uint32_t ahi[8][4], const uint32_t alo[8][4],
                                          uint32_t sb, int l) {
    const int kk   = ((l >> 3) & 1) * 8 + (l & 7);   // k-row within 16-chunk for this lane
    const int sxr  = kk & 7;                          // swizzle term
    const int nadd = l >> 4;                          // tile select (x4: lanes 16-31 -> nt+1)
    const uint32_t rowbase = sb + (uint32_t)(kk * 256);
#pragma unroll
    for (int kc = 0; kc < 8; kc++) {
        uint32_t base = rowbase + (uint32_t)(kc * 4096);
#pragma unroll
        for (int p = 0; p < 8; p++) {
            int ntx = 2 * p + nadd;
            uint32_t b4[4];
            ldsm_x4_t(b4, base + (uint32_t)((ntx ^ sxr) << 4));      // W_hi tiles 2p,2p+1
            mma16816(c[2 * p],     ahi[kc], b4);
            mma16816(c[2 * p + 1], ahi[kc], b4 + 2);
            mma16816(c[2 * p],     alo[kc], b4);
            mma16816(c[2 * p + 1], alo[kc], b4 + 2);
        }
#pragma unroll
        for (int p = 0; p < 8; p++) {
            int ntx = 2 * p + nadd;
            uint32_t b4[4];
            ldsm_x4_t(b4, base + 32768u + (uint32_t)((ntx ^ sxr) << 4));  // W_lo
            mma16816(c[2 * p],     ahi[kc], b4);
            mma16816(c[2 * p + 1], ahi[kc], b4 + 2);
        }
    }
}

// GN(+relu) over rows rA,rB held in C frags; repack into next-stage A frags.
// GATHER: add qb[hi]+ctxc[wi] before GN (stage 2 of the pipeline).
template <bool GATHER>
__device__ __forceinline__ void ep_gn(float c[16][4],
                                      uint32_t ahi[8][4], uint32_t alo[8][4],
                                      const float* __restrict__ gamma,
                                      const float* __restrict__ beta,
                                      const int* hi_s, const int* wi_s,
                                      int rA, int rB, int q) {
    if (GATHER) {
        const float* qA = g_qb   + hi_s[rA] * D;
        const float* qB = g_qb   + hi_s[rB] * D;
        const float* cA = g_ctxc + wi_s[rA] * D;
        const float* cB = g_ctxc + wi_s[rB] * D;
#pragma unroll
        for (int t = 0; t < 16; t++) {
            int c0 = t * 8 + q * 2;
            float2 a1 = __ldg((const float2*)(qA + c0));
            float2 a2 = __ldg((const float2*)(cA + c0));
            float2 b1 = __ldg((const float2*)(qB + c0));
            float2 b2 = __ldg((const float2*)(cB + c0));
            c[t][0] += a1.x + a2.x;  c[t][1] += a1.y + a2.y;
            c[t][2] += b1.x + b2.x;  c[t][3] += b1.y + b2.y;
        }
    }
    float sA = 0.f, qsA = 0.f, sB = 0.f, qsB = 0.f;
#pragma unroll
    for (int t = 0; t < 16; t++) {
        sA += c[t][0] + c[t][1];
        qsA = fmaf(c[t][0], c[t][0], fmaf(c[t][1], c[t][1], qsA));
        sB += c[t][2] + c[t][3];
        qsB = fmaf(c[t][2], c[t][2], fmaf(c[t][3], c[t][3], qsB));
    }
    sA  += __shfl_xor_sync(~0u, sA, 1);  sA  += __shfl_xor_sync(~0u, sA, 2);
    qsA += __shfl_xor_sync(~0u, qsA, 1); qsA += __shfl_xor_sync(~0u, qsA, 2);
    sB  += __shfl_xor_sync(~0u, sB, 1);  sB  += __shfl_xor_sync(~0u, sB, 2);
    qsB += __shfl_xor_sync(~0u, qsB, 1); qsB += __shfl_xor_sync(~0u, qsB, 2);
    float mA = sA * (1.f / 128.f), vA = qsA * (1.f / 128.f) - mA * mA, rsA = rsqrtf(vA + EPS);
    float mB = sB * (1.f / 128.f), vB = qsB * (1.f / 128.f) - mB * mB, rsB = rsqrtf(vB + EPS);
#pragma unroll
    for (int t = 0; t < 16; t++) {
        int c0 = t * 8 + q * 2;
        float g0 = __ldg(gamma + c0), g1 = __ldg(gamma + c0 + 1);
        float b0 = __ldg(beta + c0),  b1 = __ldg(beta + c0 + 1);
        float xA0 = fmaxf(fmaf((c[t][0] - mA) * rsA, g0, b0), 0.f);
        float xA1 = fmaxf(fmaf((c[t][1] - mA) * rsA, g1, b1), 0.f);
        float xB0 = fmaxf(fmaf((c[t][2] - mB) * rsB, g0, b0), 0.f);
        float xB1 = fmaxf(fmaf((c[t][3] - mB) * rsB, g1, b1), 0.f);
        int kc = t >> 1, j = (t & 1) * 2;
        split_pack(xA0, xA1, ahi[kc][j],     alo[kc][j]);
        split_pack(xB0, xB1, ahi[kc][j + 1], alo[kc][j + 1]);
    }
}

__global__ __launch_bounds__(256, 1) void k_edge_mma(
    const float* __restrict__ agt_ctrs, const float* __restrict__ ctx_ctrs,
    const int* __restrict__ hi, const int* __restrict__ wi,
    const float* __restrict__ dist_w1, const float* __restrict__ dist_b1,
    const float* __restrict__ dist_w2, const float* __restrict__ dist_g2,
    const float* __restrict__ dist_b2,
    const float* __restrict__ ctx_w1, const float* __restrict__ ctx_g1,
    const float* __restrict__ ctx_b1,
    const float* __restrict__ ctx_w2) {
    extern __shared__ char smem[];
    const uint32_t sb = smem_u32(smem);
    const int tid = threadIdx.x;
    const int w = tid >> 5, l = tid & 31, q = l & 3;
    const int rA = w * 16 + (l >> 2);      // local edge rows owned by this lane
    const int rB = rA + 8;

    int* hi_s = (int*)(smem + SM_HIS);
    int* wi_s = (int*)(smem + SM_WIS);
    float2* d2s = (float2*)(smem + SM_D2);
    const int e0 = blockIdx.x * TRE;
    if (tid < TRE) {
        int h = hi[e0 + tid], ww = wi[e0 + tid];
        hi_s[tid] = h; wi_s[tid] = ww;
        float2 ac = ((const float2*)agt_ctrs)[h];
        float2 cc = ((const float2*)ctx_ctrs)[ww];
        d2s[tid] = make_float2(ac.x - cc.x, ac.y - cc.y);
    }
    copy_w_split(dist_w2, smem, tid);
    __syncthreads();

    // initial A = relu(d2 @ dist_w1 + b1), computed directly in fragment layout
    uint32_t ahi[8][4], alo[8][4];
    {
        float2 ddA = d2s[rA], ddB = d2s[rB];
#pragma unroll
        for (int kc = 0; kc < 8; kc++) {
#pragma unroll
            for (int h = 0; h < 2; h++) {
                int col = kc * 16 + h * 8 + q * 2;
                float w00 = __ldg(dist_w1 + col),     w01 = __ldg(dist_w1 + col + 1);
                float w10 = __ldg(dist_w1 + D + col), w11 = __ldg(dist_w1 + D + col + 1);
                float bb0 = __ldg(dist_b1 + col),     bb1 = __ldg(dist_b1 + col + 1);
                float xA0 = fmaxf(fmaf(ddA.x, w00, fmaf(ddA.y, w10, bb0)), 0.f);
                float xA1 = fmaxf(fmaf(ddA.x, w01, fmaf(ddA.y, w11, bb1)), 0.f);
                float xB0 = fmaxf(fmaf(ddB.x, w00, fmaf(ddB.y, w10, bb0)), 0.f);
                float xB1 = fmaxf(fmaf(ddB.x, w01, fmaf(ddB.y, w11, bb1)), 0.f);
                split_pack(xA0, xA1, ahi[kc][h * 2],     alo[kc][h * 2]);
                split_pack(xB0, xB1, ahi[kc][h * 2 + 1], alo[kc][h * 2 + 1]);
            }
        }
    }

    float c[16][4];
    // ---- stage 1: @ dist_w2, GN(dist_g2,b2)+relu ----
#pragma unroll
    for (int t = 0; t < 16; t++) { c[t][0] = c[t][1] = c[t][2] = c[t][3] = 0.f; }
    mma_stage(c, ahi, alo, sb, l);
    ep_gn<false>(c, ahi, alo, dist_g2, dist_b2, hi_s, wi_s, rA, rB, q);
    __syncthreads();

    // ---- stage 2: @ ctx_w1[0:128] + qb[hi] + ctxc[wi], GN(ctx_g1,b1)+relu ----
    copy_w_split(ctx_w1, smem, tid);
    __syncthreads();
#pragma unroll
    for (int t = 0; t < 16; t++) { c[t][0] = c[t][1] = c[t][2] = c[t][3] = 0.f; }
    mma_stage(c, ahi, alo, sb, l);
    ep_gn<true>(c, ahi, alo, ctx_g1, ctx_b1, hi_s, wi_s, rA, rB, q);
    __syncthreads();

    // ---- stage 3: @ ctx_w2, scatter-add ----
    copy_w_split(ctx_w2, smem, tid);
    __syncthreads();
#pragma unroll
    for (int t = 0; t < 16; t++) { c[t][0] = c[t][1] = c[t][2] = c[t][3] = 0.f; }
    mma_stage(c, ahi, alo, sb, l);
    {
        float* baseA = g_acc + hi_s[rA] * D;
        float* baseB = g_acc + hi_s[rB] * D;
        const bool even = (q & 1) == 0;
#pragma unroll
        for (int t = 0; t < 16; t++) {
            float x0 = __shfl_xor_sync(~0u, c[t][0], 1);
            float x1 = __shfl_xor_sync(~0u, c[t][1], 1);
            float x2 = __shfl_xor_sync(~0u, c[t][2], 1);
            float x3 = __shfl_xor_sync(~0u, c[t][3], 1);
            if (even) red4(baseA + t * 8 + q * 2,       c[t][0], c[t][1], x0, x1);
            else      red4(baseB + t * 8 + (q - 1) * 2, x2, x3, c[t][2], c[t][3]);
        }
    }
}

// ---------------------------------------------------------------------------
// FFMA node kernels (round-1, known good)
// ---------------------------------------------------------------------------
__device__ __forceinline__ void gemm_tile(const float* in_s, const float* __restrict__ W,
                                          float* wbuf, float acc[8][4], int e0, int c4, int tid) {
    const float4* Wg = reinterpret_cast<const float4*>(W);
    float4* wb = reinterpret_cast<float4*>(wbuf);
    for (int kb = 0; kb < D; kb += KC) {
        __syncthreads();
        wb[tid]      = Wg[kb * (D / 4) + tid];
        wb[tid + NT] = Wg[kb * (D / 4) + tid + NT];
        __syncthreads();
#pragma unroll
        for (int kk = 0; kk < KC; kk++) {
            float4 w = wb[kk * (D / 4) + c4];
#pragma unroll
            for (int i = 0; i < 8; i++) {
                float h = in_s[(e0 + i) * D + kb + kk];
                acc[i][0] = fmaf(h, w.x, acc[i][0]);
                acc[i][1] = fmaf(h, w.y, acc[i][1]);
                acc[i][2] = fmaf(h, w.z, acc[i][2]);
                acc[i][3] = fmaf(h, w.w, acc[i][3]);
            }
        }
    }
}

__device__ __forceinline__ void zero_acc(float acc[8][4]) {
#pragma unroll
    for (int i = 0; i < 8; i++)
#pragma unroll
        for (int j = 0; j < 4; j++) acc[i][j] = 0.f;
}

__device__ __forceinline__ void store_acc(float* io, const float acc[8][4], int e0, int c4) {
#pragma unroll
    for (int i = 0; i < 8; i++) {
        float4 v = make_float4(acc[i][0], acc[i][1], acc[i][2], acc[i][3]);
        *reinterpret_cast<float4*>(&io[(e0 + i) * D + c4 * 4]) = v;
    }
}

__device__ __forceinline__ void gn_rows(float* io, const float* __restrict__ g,
                                        const float* __restrict__ b, bool do_relu, int tid) {
    int lane = tid & 31, w = tid >> 5;
    for (int r = w; r < TR; r += 8) {
        float v[4], s = 0.f, sq = 0.f;
#pragma unroll
        for (int j = 0; j < 4; j++) {
            v[j] = io[r * D + lane + 32 * j];
            s += v[j]; sq += v[j] * v[j];
        }
#pragma unroll
        for (int o = 16; o > 0; o >>= 1) {
            s  += __shfl_xor_sync(0xffffffffu, s, o);
            sq += __shfl_xor_sync(0xffffffffu, sq, o);
        }
        float mean = s * (1.f / D);
        float var  = sq * (1.f / D) - mean * mean;
        float rstd = rsqrtf(var + EPS);
#pragma unroll
        for (int j = 0; j < 4; j++) {
            int c = lane + 32 * j;
            float x = (v[j] - mean) * rstd * g[c] + b[c];
            io[r * D + c] = do_relu ? fmaxf(x, 0.f) : x;
        }
    }
}

__global__ __launch_bounds__(NT) void k_qb(const float* __restrict__ agts,
                                           const float* __restrict__ query_w,
                                           const float* __restrict__ query_g,
                                           const float* __restrict__ query_b,
                                           const float* __restrict__ ctx_w1) {
    __shared__ float io[TR * D];
    __shared__ float wbuf[KC * D];
    int tid = threadIdx.x;
    int r0 = blockIdx.x * TR;
    int lane = tid & 31, wid = tid >> 5;
    int c4 = lane, e0 = wid * 8;

    for (int idx = tid; idx < TR * D; idx += NT) io[idx] = agts[r0 * D + idx];

    float acc[8][4];
    zero_acc(acc);
    gemm_tile(io, query_w, wbuf, acc, e0, c4, tid);
    __syncthreads();
    store_acc(io, acc, e0, c4);
    __syncthreads();
    gn_rows(io, query_g, query_b, true, tid);
    __syncthreads();

    zero_acc(acc);
    gemm_tile(io, ctx_w1 + D * D, wbuf, acc, e0, c4, tid);
#pragma unroll
    for (int i = 0; i < 8; i++) {
        float4 v = make_float4(acc[i][0], acc[i][1], acc[i][2], acc[i][3]);
        *reinterpret_cast<float4*>(&g_qb[(r0 + e0 + i) * D + c4 * 4]) = v;
    }
}

__global__ __launch_bounds__(NT) void k_accinit(const float* __restrict__ agts,
                                                const float* __restrict__ agt_w) {
    __shared__ float io[TR * D];
    __shared__ float wbuf[KC * D];
    int tid = threadIdx.x;
    int r0 = blockIdx.x * TR;
    int lane = tid & 31, wid = tid >> 5;
    int c4 = lane, e0 = wid * 8;

    for (int idx = tid; idx < TR * D; idx += NT) io[idx] = agts[r0 * D + idx];

    float acc[8][4];
    zero_acc(acc);
    gemm_tile(io, agt_w, wbuf, acc, e0, c4, tid);
#pragma unroll
    for (int i = 0; i < 8; i++) {
        float4 v = make_float4(acc[i][0], acc[i][1], acc[i][2], acc[i][3]);
        *reinterpret_cast<float4*>(&g_acc[(r0 + e0 + i) * D + c4 * 4]) = v;
    }
}

__global__ __launch_bounds__(NT) void k_ctxc(const float* __restrict__ ctx,
                                             const float* __restrict__ ctx_w1) {
    __shared__ float io[TR * D];
    __shared__ float wbuf[KC * D];
    int tid = threadIdx.x;
    int r0 = blockIdx.x * TR;
    int lane = tid & 31, wid = tid >> 5;
    int c4 = lane, e0 = wid * 8;

    for (int idx = tid; idx < TR * D; idx += NT) io[idx] = ctx[r0 * D + idx];

    float acc[8][4];
    zero_acc(acc);
    gemm_tile(io, ctx_w1 + 2 * D * D, wbuf, acc, e0, c4, tid);
#pragma unroll
    for (int i = 0; i < 8; i++) {
        float4 v = make_float4(acc[i][0], acc[i][1], acc[i][2], acc[i][3]);
        *reinterpret_cast<float4*>(&g_ctxc[(r0 + e0 + i) * D + c4 * 4]) = v;
    }
}

__global__ __launch_bounds__(NT) void k_final(const float* __restrict__ agts,
                                              const float* __restrict__ norm_g,
                                              const float* __restrict__ norm_b,
                                              const float* __restrict__ lin_w,
                                              const float* __restrict__ lin_g,
                                              const float* __restrict__ lin_b,
                                              float* __restrict__ out) {
    __shared__ float io[TR * D];
    __shared__ float wbuf[KC * D];
    int tid = threadIdx.x;
    int r0 = blockIdx.x * TR;
    int lane = tid & 31, wid = tid >> 5;
    int c4 = lane, e0 = wid * 8;

    for (int idx = tid; idx < TR * D; idx += NT) io[idx] = g_acc[r0 * D + idx];
    __syncthreads();
    gn_rows(io, norm_g, norm_b, true, tid);
    __syncthreads();

    float acc[8][4];
    zero_acc(acc);
    gemm_tile(io, lin_w, wbuf, acc, e0, c4, tid);
    __syncthreads();
    store_acc(io, acc, e0, c4);
    __syncthreads();

    for (int r = wid; r < TR; r += 8) {
        float v[4], s = 0.f, sq = 0.f;
#pragma unroll
        for (int j = 0; j < 4; j++) {
            v[j] = io[r * D + lane + 32 * j];
            s += v[j]; sq += v[j] * v[j];
        }
#pragma unroll
        for (int o = 16; o > 0; o >>= 1) {
            s  += __shfl_xor_sync(0xffffffffu, s, o);
            sq += __shfl_xor_sync(0xffffffffu, sq, o);
        }
        float mean = s * (1.f / D);
        float var  = sq * (1.f / D) - mean * mean;
        float rstd = rsqrtf(var + EPS);
#pragma unroll
        for (int j = 0; j < 4; j++) {
            int c = lane + 32 * j;
            float x = (v[j] - mean) * rstd * lin_g[c] + lin_b[c];
            float res = agts[(r0 + r) * D + c];
            out[(r0 + r) * D + c] = fmaxf(x + res, 0.f);
        }
    }
}

// ---------------------------------------------------------------------------
extern "C" void kernel_launch(void* const* d_in, const int* in_sizes, int n_in,
                              void* d_out, int out_size) {
    const float* agts     = (const float*)d_in[0];
    const float* ctx      = (const float*)d_in[1];
    const float* agt_ctrs = (const float*)d_in[2];
    const float* ctx_ctrs = (const float*)d_in[3];
    const int*   hi       = (const int*)d_in[4];
    const int*   wi       = (const int*)d_in[5];
    const float* dist_w1  = (const float*)d_in[6];
    const float* dist_b1  = (const float*)d_in[7];
    const float* dist_w2  = (const float*)d_in[8];
    const float* dist_g2  = (const float*)d_in[9];
    const float* dist_b2  = (const float*)d_in[10];
    const float* query_w  = (const float*)d_in[11];
    const float* query_g  = (const float*)d_in[12];
    const float* query_b  = (const float*)d_in[13];
    const float* ctx_w1   = (const float*)d_in[14];
    const float* ctx_g1   = (const float*)d_in[15];
    const float* ctx_b1   = (const float*)d_in[16];
    const float* ctx_w2   = (const float*)d_in[17];
    const float* agt_w    = (const float*)d_in[18];
    const float* norm_g   = (const float*)d_in[19];
    const float* norm_b   = (const float*)d_in[20];
    const float* lin_w    = (const float*)d_in[21];
    const float* lin_g    = (const float*)d_in[22];
    const float* lin_b    = (const float*)d_in[23];
    float* out = (float*)d_out;

    cudaFuncSetAttribute(k_edge_mma, cudaFuncAttributeMaxDynamicSharedMemorySize, SMEM_EDGE);

    k_qb<<<NA / TR, NT>>>(agts, query_w, query_g, query_b, ctx_w1);
    k_accinit<<<NA / TR, NT>>>(agts, agt_w);
    k_ctxc<<<NC / TR, NT>>>(ctx, ctx_w1);
    k_edge_mma<<<NE / TRE, 256, SMEM_EDGE>>>(agt_ctrs, ctx_ctrs, hi, wi,
                                             dist_w1, dist_b1,
                                             dist_w2, dist_g2, dist_b2,
                                             ctx_w1, ctx_g1, ctx_b1, ctx_w2);
    k_final<<<NA / TR, NT>>>(agts, norm_g, norm_b, lin_w, lin_g, lin_b, out);
}